// round 16
// baseline (speedup 1.0000x reference)
#include <cuda_runtime.h>
#include <cuda_fp16.h>
#include <cstdint>

// ---------------------------------------------------------------------------
// QuanvolutionHybrid: closed-form quantum features + conv/bn/residual + fc.
//   Z0 = cos(t4)cos(t0+p0) - sin(t4)sin(t0+p0)sin(p1)
//   Z1 = cos(t0+p0) cos(t1) cos(p1)
//   Z2 = Z1 * cos(p2)
//   Z3 = cos(t3) cos(p2) cos(p3)      (qw[2] provably unused)
// fp16 intermediates; hoisted global loads; conv inner loop uses aligned
// vector LDS (pairs land in register pairs, no pack MOVs); stats zeroing
// folded into pipeline (k1 zeroes stats2, k_fc zeroes stats1).
// ---------------------------------------------------------------------------

#define MAXB 4096
#define E    784
#define NBIN 32
#define FST  20               // tile row stride (floats); rows 16B-aligned
#define FIMG (4 * 16 * FST)   // 1280 floats per image tile

typedef unsigned long long u64;

__device__ __half f_h [MAXB * E];
__device__ __half t1_h[MAXB * E];
__device__ __half t2_h[MAXB * E];
__device__ float stats1_g[NBIN * 8];   // zero at load; k_fc re-zeroes each run
__device__ float stats2_g[NBIN * 8];   // zero at load; k1  re-zeroes each run

__device__ __forceinline__ u64 fma2(u64 a, u64 b, u64 c) {
    u64 d;
    asm("fma.rn.f32x2 %0, %1, %2, %3;" : "=l"(d) : "l"(a), "l"(b), "l"(c));
    return d;
}
__device__ __forceinline__ u64 add2(u64 a, u64 b) {
    u64 d;
    asm("add.rn.f32x2 %0, %1, %2;" : "=l"(d) : "l"(a), "l"(b));
    return d;
}
__device__ __forceinline__ u64 pack2(float lo, float hi) {
    u64 d;
    asm("mov.b64 %0, {%1, %2};" : "=l"(d) : "f"(lo), "f"(hi));
    return d;
}
__device__ __forceinline__ float2 unpack2(u64 v) {
    float lo, hi;
    asm("mov.b64 {%0, %1}, %2;" : "=f"(lo), "=f"(hi) : "l"(v));
    return make_float2(lo, hi);
}
// (hi(a), lo(b)) -> odd pixel-pair from two adjacent even pairs (2 MOVs)
__device__ __forceinline__ u64 mix2(u64 a, u64 b) {
    float2 ua = unpack2(a), ub = unpack2(b);
    return pack2(ua.y, ub.x);
}

union HPack { uint2 u; __half2 h[2]; };

// wt2: duplicated pairs; u64 index i=(ic*3+kh)*12+kw*4+oc holds (w,w).
__device__ __forceinline__ void stage_weights(const float* __restrict__ w,
                                              float* wt2, int t, int nthr) {
    for (int i = t; i < 144; i += nthr) {
        int oc = i & 3, rest = i >> 2;
        int kw = rest % 3, kh = (rest / 3) % 3, ic = rest / 9;
        float v = w[((oc * 4 + ic) * 3 + kh) * 3 + kw];
        wt2[2 * i] = v;
        wt2[2 * i + 1] = v;
    }
}

// Warp computes 2 output channels (oc=half*2,half*2+1).  Lane<28:
// row=lane>>1, seg=lane&1, w0=seg*8 (seg0: px0-7 = 4 pairs; seg1: px8-13 =
// 3 pairs, 4th pair garbage from zero padding).  Even input pairs arrive
// pre-paired via LDS.128/LDS.64; odd pairs built with mix2.  Staging stores
// are STS.64 from accumulators; stats via f32x2 pair math.
// Contains __syncthreads: call from ALL threads of the block.
__device__ __forceinline__ void warp_conv(
    float* myfz, const float* __restrict__ wt2,
    uint2* __restrict__ dst, float* __restrict__ stats,
    int b, int lane, int half, bool act)
{
    int row = lane >> 1, seg = lane & 1, w0 = seg * 8;
    u64 acc[2][4];
    #pragma unroll
    for (int o = 0; o < 2; o++)
        #pragma unroll
        for (int p = 0; p < 4; p++) acc[o][p] = 0ull;

    if (act && lane < 28) {
        const ulonglong2* wp2 = reinterpret_cast<const ulonglong2*>(wt2);
        #pragma unroll
        for (int ic = 0; ic < 4; ic++) {
            #pragma unroll
            for (int kh = 0; kh < 3; kh++) {
                const float* rowp = myfz + (ic * 16 + row + kh) * FST + w0;
                ulonglong2 V0 = *reinterpret_cast<const ulonglong2*>(rowp);
                ulonglong2 V1 = *reinterpret_cast<const ulonglong2*>(rowp + 4);
                u64 PE4 = *reinterpret_cast<const u64*>(rowp + 8);
                u64 PE0 = V0.x, PE1 = V0.y, PE2 = V1.x, PE3 = V1.y;
                u64 PO0 = mix2(PE0, PE1);
                u64 PO1 = mix2(PE1, PE2);
                u64 PO2 = mix2(PE2, PE3);
                u64 PO3 = mix2(PE3, PE4);
                int wbase = (ic * 3 + kh) * 6 + half;
                ulonglong2 wv0 = wp2[wbase];        // kw=0 (oc0,oc1)
                ulonglong2 wv1 = wp2[wbase + 2];    // kw=1
                ulonglong2 wv2 = wp2[wbase + 4];    // kw=2
                acc[0][0] = fma2(PE0, wv0.x, acc[0][0]);
                acc[0][1] = fma2(PE1, wv0.x, acc[0][1]);
                acc[0][2] = fma2(PE2, wv0.x, acc[0][2]);
                acc[0][3] = fma2(PE3, wv0.x, acc[0][3]);
                acc[1][0] = fma2(PE0, wv0.y, acc[1][0]);
                acc[1][1] = fma2(PE1, wv0.y, acc[1][1]);
                acc[1][2] = fma2(PE2, wv0.y, acc[1][2]);
                acc[1][3] = fma2(PE3, wv0.y, acc[1][3]);
                acc[0][0] = fma2(PO0, wv1.x, acc[0][0]);
                acc[0][1] = fma2(PO1, wv1.x, acc[0][1]);
                acc[0][2] = fma2(PO2, wv1.x, acc[0][2]);
                acc[0][3] = fma2(PO3, wv1.x, acc[0][3]);
                acc[1][0] = fma2(PO0, wv1.y, acc[1][0]);
                acc[1][1] = fma2(PO1, wv1.y, acc[1][1]);
                acc[1][2] = fma2(PO2, wv1.y, acc[1][2]);
                acc[1][3] = fma2(PO3, wv1.y, acc[1][3]);
                acc[0][0] = fma2(PE1, wv2.x, acc[0][0]);
                acc[0][1] = fma2(PE2, wv2.x, acc[0][1]);
                acc[0][2] = fma2(PE3, wv2.x, acc[0][2]);
                acc[0][3] = fma2(PE4, wv2.x, acc[0][3]);
                acc[1][0] = fma2(PE1, wv2.y, acc[1][0]);
                acc[1][1] = fma2(PE2, wv2.y, acc[1][1]);
                acc[1][2] = fma2(PE3, wv2.y, acc[1][2]);
                acc[1][3] = fma2(PE4, wv2.y, acc[1][3]);
            }
        }
    }
    __syncthreads();                 // tile reads complete block-wide

    float s[4] = {0.f, 0.f, 0.f, 0.f};
    if (act && lane < 28) {
        #pragma unroll
        for (int o = 0; o < 2; o++) {
            int oc = half * 2 + o;
            u64* op = reinterpret_cast<u64*>(myfz + oc * 196 + row * 14 + w0);
            op[0] = acc[o][0];
            op[1] = acc[o][1];
            op[2] = acc[o][2];
            if (seg == 0) op[3] = acc[o][3];
            u64 sum2 = add2(add2(acc[o][0], acc[o][1]), acc[o][2]);
            u64 sq2  = fma2(acc[o][0], acc[o][0], 0ull);
            sq2      = fma2(acc[o][1], acc[o][1], sq2);
            sq2      = fma2(acc[o][2], acc[o][2], sq2);
            if (seg == 0) {
                sum2 = add2(sum2, acc[o][3]);
                sq2  = fma2(acc[o][3], acc[o][3], sq2);
            }
            float2 us = unpack2(sum2), uq = unpack2(sq2);
            s[o]     = us.x + us.y;
            s[2 + o] = uq.x + uq.y;
        }
    }
    __syncwarp();
    if (act) {
        const float4* ob4 = reinterpret_cast<const float4*>(myfz);
        #pragma unroll
        for (int it = 0; it < 4; it++) {
            int j = it * 32 + lane;
            if (j < 98) {
                int i = half * 98 + j;
                float4 v = ob4[i];
                HPack pk;
                pk.h[0] = __floats2half2_rn(v.x, v.y);
                pk.h[1] = __floats2half2_rn(v.z, v.w);
                dst[i] = pk.u;
            }
        }
    }
    #pragma unroll
    for (int off = 16; off; off >>= 1)
        #pragma unroll
        for (int c = 0; c < 4; c++)
            s[c] += __shfl_down_sync(0xffffffffu, s[c], off);
    if (act && lane == 0) {
        int base = (b & (NBIN - 1)) * 8 + half * 2;
        atomicAdd(&stats[base],     s[0]);
        atomicAdd(&stats[base + 1], s[1]);
        atomicAdd(&stats[base + 4], s[2]);
        atomicAdd(&stats[base + 5], s[3]);
    }
}

__device__ __forceinline__ void bn_prologue(
    const float* __restrict__ stats, const float* __restrict__ gamma,
    const float* __restrict__ beta, float* sums8, float* sc, float* bi,
    int t, float Ninv)
{
    if (t < 8) {
        float s = 0.f;
        #pragma unroll
        for (int bin = 0; bin < NBIN; bin++) s += stats[bin * 8 + t];
        sums8[t] = s;
    }
    __syncthreads();
    if (t < 4) {
        float mean = sums8[t] * Ninv;
        float var  = sums8[4 + t] * Ninv - mean * mean;
        float s    = gamma[t] * rsqrtf(var + 1e-5f);
        sc[t] = s;
        bi[t] = beta[t] - mean * s;
    }
    __syncthreads();
}

// K1: quantum + conv1 + stats1.  2 warps/image, 2 images per 128-thr block.
// Block 0 also zeroes stats2 for this run (nothing reads stats2 during k1).
__global__ void __launch_bounds__(128) k_quanv_conv1(
    const float* __restrict__ x, const float* __restrict__ qw,
    const float* __restrict__ w1, int B)
{
    __shared__ __align__(16) float fz[2 * FIMG];
    __shared__ __align__(16) float wt2[288];
    int t = threadIdx.x, warp = t >> 5, lane = t & 31;
    int m = warp >> 1, half = warp & 1;
    int b = blockIdx.x * 2 + m;
    bool act = (b < B);

    if (blockIdx.x == 0) {           // fold k_init: zero stats2
        stats2_g[t] = 0.f;
        stats2_g[t + 128] = 0.f;
    }

    // --- hoisted x loads ---
    float2 xr0[4], xr1[4];
    const float* xb = x + (size_t)b * E;
    #pragma unroll
    for (int it = 0; it < 4; it++) {
        int j = it * 32 + lane;
        if (act && j < 98) {
            int p = half * 98 + j;
            int i = p / 14, jj = p % 14;
            xr0[it] = *reinterpret_cast<const float2*>(xb + i * 56 + jj * 2);
            xr1[it] = *reinterpret_cast<const float2*>(xb + i * 56 + 28 + jj * 2);
        }
    }

    stage_weights(w1, wt2, t, 128);
    float4* tz = reinterpret_cast<float4*>(fz);
    #pragma unroll
    for (int k = 0; k < 5; k++)
        tz[t + 128 * k] = make_float4(0.f, 0.f, 0.f, 0.f);
    __syncthreads();

    float* myfz = fz + m * FIMG;
    if (act) {
        float q0 = qw[0], q1 = qw[1], q3 = qw[3], q4 = qw[4];
        float ct1 = __cosf(q1), ct3 = __cosf(q3);
        float st4, ct4; __sincosf(q4, &st4, &ct4);
        uint2* fdst = reinterpret_cast<uint2*>(f_h + (size_t)b * E);
        #pragma unroll
        for (int it = 0; it < 4; it++) {
            int j = it * 32 + lane;
            if (j < 98) {
                int p = half * 98 + j;
                float sa, ca;   __sincosf(q0 + xr0[it].x, &sa, &ca);
                float sp1, cp1; __sincosf(xr0[it].y, &sp1, &cp1);
                float cp2 = __cosf(xr1[it].x), cp3 = __cosf(xr1[it].y);

                float m0 = ct4 * ca - st4 * sa * sp1;
                float m1 = ca * ct1 * cp1;
                float m2 = m1 * cp2;
                float m3 = ct3 * cp2 * cp3;

                HPack pk;
                pk.h[0] = __floats2half2_rn(m0, m1);
                pk.h[1] = __floats2half2_rn(m2, m3);
                fdst[p] = pk.u;

                float mv[4] = {m0, m1, m2, m3};
                #pragma unroll
                for (int q = 0; q < 4; q++) {
                    int e = p * 4 + q, c = e / 196, rr = e % 196;
                    myfz[(c * 16 + rr / 14 + 1) * FST + rr % 14 + 1] = mv[q];
                }
            }
        }
    }
    __syncthreads();
    warp_conv(myfz, wt2, reinterpret_cast<uint2*>(t1_h + (size_t)b * E),
              stats1_g, b, lane, half, act);
}

// K2: bn1+relu + conv2 + stats2.  Same shape; t1 loads hoisted.
__global__ void __launch_bounds__(128) k_conv2(
    const float* __restrict__ w2, const float* __restrict__ g1,
    const float* __restrict__ be1, int B)
{
    __shared__ __align__(16) float fz[2 * FIMG];
    __shared__ __align__(16) float wt2[288];
    __shared__ float sums8[8], sc[4], bi[4];
    int t = threadIdx.x, warp = t >> 5, lane = t & 31;
    int m = warp >> 1, half = warp & 1;
    int b = blockIdx.x * 2 + m;
    bool act = (b < B);

    // --- hoisted t1 loads ---
    uint2 tv[4];
    const uint2* src = reinterpret_cast<const uint2*>(t1_h + (size_t)b * E);
    #pragma unroll
    for (int it = 0; it < 4; it++) {
        int j = it * 32 + lane;
        if (act && j < 98) tv[it] = src[half * 98 + j];
    }

    stage_weights(w2, wt2, t, 128);
    float4* tz = reinterpret_cast<float4*>(fz);
    #pragma unroll
    for (int k = 0; k < 5; k++)
        tz[t + 128 * k] = make_float4(0.f, 0.f, 0.f, 0.f);

    bn_prologue(stats1_g, g1, be1, sums8, sc, bi, t, 1.f / ((float)B * 196.f));

    float* myfz = fz + m * FIMG;
    if (act) {
        #pragma unroll
        for (int it = 0; it < 4; it++) {
            int j = it * 32 + lane;
            if (j < 98) {
                int e4 = half * 98 + j;
                HPack pk; pk.u = tv[it];
                float2 lo = __half22float2(pk.h[0]);
                float2 hi = __half22float2(pk.h[1]);
                int c = e4 / 49;
                float s = sc[c], o = bi[c];
                float vv[4] = { fmaxf(lo.x*s+o, 0.f), fmaxf(lo.y*s+o, 0.f),
                                fmaxf(hi.x*s+o, 0.f), fmaxf(hi.y*s+o, 0.f) };
                int rr = (e4 * 4) % 196;
                #pragma unroll
                for (int q = 0; q < 4; q++) {
                    int rq = rr + q;
                    myfz[(c * 16 + rq / 14 + 1) * FST + rq % 14 + 1] = vv[q];
                }
            }
        }
    }
    __syncthreads();
    warp_conv(myfz, wt2, reinterpret_cast<uint2*>(t2_h + (size_t)b * E),
              stats2_g, b, lane, half, act);
}

// K3: bn2 + residual + relu + fc + log_softmax.  2 images per warp (each fcw
// load feeds both), 8 images per 128-thr block.  Image A's t2/f hoisted;
// image B loaded inline.  Block 0 zeroes stats1 for the next run.
__global__ void __launch_bounds__(128) k_fc(
    const float* __restrict__ g2, const float* __restrict__ be2,
    const float* __restrict__ fcw, const float* __restrict__ fcb,
    float* __restrict__ out, int B)
{
    __shared__ float sums8[8], sc[4], bi[4];
    int t = threadIdx.x, warp = t >> 5, lane = t & 31;
    int b0 = blockIdx.x * 8 + warp * 2;
    bool a0 = (b0 < B), a1 = (b0 + 1 < B);
    int c0 = a0 ? b0 : 0, c1 = a1 ? b0 + 1 : c0;

    if (blockIdx.x == 0) {           // fold k_init: zero stats1 (dead here)
        stats1_g[t] = 0.f;
        stats1_g[t + 128] = 0.f;
    }

    // --- hoisted image-A loads ---
    uint2 tvA[7], fvA[7];
    const uint2* tA = reinterpret_cast<const uint2*>(t2_h + (size_t)c0 * E);
    const uint2* fA = reinterpret_cast<const uint2*>(f_h  + (size_t)c0 * E);
    #pragma unroll
    for (int it = 0; it < 7; it++) {
        int i = it * 32 + lane;
        if (a0 && i < 196) { tvA[it] = tA[i]; fvA[it] = fA[i]; }
    }

    bn_prologue(stats2_g, g2, be2, sums8, sc, bi, t, 1.f / ((float)B * 196.f));
    if (!a0) return;

    const uint2* tB = reinterpret_cast<const uint2*>(t2_h + (size_t)c1 * E);
    const uint2* fB = reinterpret_cast<const uint2*>(f_h  + (size_t)c1 * E);
    const float4* fw4 = reinterpret_cast<const float4*>(fcw);

    u64 accA[10], accB[10];
    #pragma unroll
    for (int k = 0; k < 10; k++) { accA[k] = 0ull; accB[k] = 0ull; }

    #pragma unroll
    for (int it = 0; it < 7; it++) {
        int i = it * 32 + lane;
        if (i < 196) {
            int c = i / 49;
            float s = sc[c], o = bi[c];

            HPack ta; ta.u = tvA[it];
            HPack fa; fa.u = fvA[it];
            float2 tl = __half22float2(ta.h[0]), th = __half22float2(ta.h[1]);
            float2 fl = __half22float2(fa.h[0]), fh = __half22float2(fa.h[1]);
            u64 A1 = pack2(fmaxf(tl.x*s+o+fl.x, 0.f), fmaxf(tl.y*s+o+fl.y, 0.f));
            u64 A2 = pack2(fmaxf(th.x*s+o+fh.x, 0.f), fmaxf(th.y*s+o+fh.y, 0.f));

            HPack tb; tb.u = tB[i];
            HPack fb; fb.u = fB[i];
            float2 ul = __half22float2(tb.h[0]), uh = __half22float2(tb.h[1]);
            float2 gl = __half22float2(fb.h[0]), gh = __half22float2(fb.h[1]);
            u64 B1 = pack2(fmaxf(ul.x*s+o+gl.x, 0.f), fmaxf(ul.y*s+o+gl.y, 0.f));
            u64 B2 = pack2(fmaxf(uh.x*s+o+gh.x, 0.f), fmaxf(uh.y*s+o+gh.y, 0.f));

            #pragma unroll
            for (int k = 0; k < 10; k++) {
                float4 wv = __ldg(&fw4[k * 196 + i]);
                u64 w1p = pack2(wv.x, wv.y), w2p = pack2(wv.z, wv.w);
                accA[k] = fma2(A1, w1p, accA[k]);
                accA[k] = fma2(A2, w2p, accA[k]);
                accB[k] = fma2(B1, w1p, accB[k]);
                accB[k] = fma2(B2, w2p, accB[k]);
            }
        }
    }
    float sA[10], sB[10];
    #pragma unroll
    for (int k = 0; k < 10; k++) {
        float2 ua = unpack2(accA[k]); sA[k] = ua.x + ua.y;
        float2 ub = unpack2(accB[k]); sB[k] = ub.x + ub.y;
    }
    #pragma unroll
    for (int off = 16; off; off >>= 1)
        #pragma unroll
        for (int k = 0; k < 10; k++) {
            sA[k] += __shfl_down_sync(0xffffffffu, sA[k], off);
            sB[k] += __shfl_down_sync(0xffffffffu, sB[k], off);
        }

    if (lane == 0) {
        float lg[10], mx = -1e30f;
        #pragma unroll
        for (int k = 0; k < 10; k++) {
            lg[k] = sA[k] + fcb[k];
            mx = fmaxf(mx, lg[k]);
        }
        float se = 0.f;
        #pragma unroll
        for (int k = 0; k < 10; k++) se += expf(lg[k] - mx);
        float lse = mx + logf(se);
        #pragma unroll
        for (int k = 0; k < 10; k++) out[(size_t)b0 * 10 + k] = lg[k] - lse;

        if (a1) {
            mx = -1e30f;
            #pragma unroll
            for (int k = 0; k < 10; k++) {
                lg[k] = sB[k] + fcb[k];
                mx = fmaxf(mx, lg[k]);
            }
            se = 0.f;
            #pragma unroll
            for (int k = 0; k < 10; k++) se += expf(lg[k] - mx);
            lse = mx + logf(se);
            #pragma unroll
            for (int k = 0; k < 10; k++)
                out[(size_t)(b0 + 1) * 10 + k] = lg[k] - lse;
        }
    }
}

extern "C" void kernel_launch(void* const* d_in, const int* in_sizes, int n_in,
                              void* d_out, int out_size)
{
    const float* x   = (const float*)d_in[0];
    const float* qw  = (const float*)d_in[1];
    const float* w1  = (const float*)d_in[2];
    const float* g1  = (const float*)d_in[3];
    const float* be1 = (const float*)d_in[4];
    const float* w2  = (const float*)d_in[5];
    const float* g2  = (const float*)d_in[6];
    const float* be2 = (const float*)d_in[7];
    const float* fcw = (const float*)d_in[8];
    const float* fcb = (const float*)d_in[9];
    float* out = (float*)d_out;

    int B = in_sizes[0] / E;
    if (B > MAXB) B = MAXB;

    k_quanv_conv1<<<(B + 1) / 2, 128>>>(x, qw, w1, B);
    k_conv2<<<(B + 1) / 2, 128>>>(w2, g1, be1, B);
    k_fc<<<(B + 7) / 8, 128>>>(g2, be2, fcw, fcb, out, B);
}

// round 17
// speedup vs baseline: 1.0046x; 1.0046x over previous
#include <cuda_runtime.h>
#include <cuda_fp16.h>
#include <cstdint>

// ---------------------------------------------------------------------------
// QuanvolutionHybrid: closed-form quantum features + conv/bn/residual + fc.
//   Z0 = cos(t4)cos(t0+p0) - sin(t4)sin(t0+p0)sin(p1)
//   Z1 = cos(t0+p0) cos(t1) cos(p1)
//   Z2 = Z1 * cos(p2)
//   Z3 = cos(t3) cos(p2) cos(p3)      (qw[2] provably unused)
// fp16 intermediates; hoisted global loads; 1 warp per image computes ALL
// 4 output channels (halves smem-crossbar reads, no conv-path barriers);
// stats zeroing folded into pipeline (k1 zeroes stats2, k_fc zeroes stats1).
// ---------------------------------------------------------------------------

#define MAXB 4096
#define E    784
#define NBIN 32
#define FST  17
#define FIMG (4 * 16 * FST)   // 1088 floats per image tile

typedef unsigned long long u64;

__device__ __half f_h [MAXB * E];
__device__ __half t1_h[MAXB * E];
__device__ __half t2_h[MAXB * E];
__device__ float stats1_g[NBIN * 8];   // zero at load; k_fc re-zeroes each run
__device__ float stats2_g[NBIN * 8];   // zero at load; k1  re-zeroes each run

__device__ __forceinline__ u64 fma2(u64 a, u64 b, u64 c) {
    u64 d;
    asm("fma.rn.f32x2 %0, %1, %2, %3;" : "=l"(d) : "l"(a), "l"(b), "l"(c));
    return d;
}
__device__ __forceinline__ u64 pack2(float lo, float hi) {
    u64 d;
    asm("mov.b64 %0, {%1, %2};" : "=l"(d) : "f"(lo), "f"(hi));
    return d;
}
__device__ __forceinline__ float2 unpack2(u64 v) {
    float lo, hi;
    asm("mov.b64 {%0, %1}, %2;" : "=f"(lo), "=f"(hi) : "l"(v));
    return make_float2(lo, hi);
}

union HPack { uint2 u; __half2 h[2]; };

// wt2: duplicated pairs; u64 index i=(ic*3+kh)*12+kw*4+oc holds (w,w).
__device__ __forceinline__ void stage_weights(const float* __restrict__ w,
                                              float* wt2, int t, int nthr) {
    for (int i = t; i < 144; i += nthr) {
        int oc = i & 3, rest = i >> 2;
        int kw = rest % 3, kh = (rest / 3) % 3, ic = rest / 9;
        float v = w[((oc * 4 + ic) * 3 + kh) * 3 + kw];
        wt2[2 * i] = v;
        wt2[2 * i + 1] = v;
    }
}

// One warp computes ALL 4 output channels of the 3x3 conv on its own image
// tile (fully warp-synchronous: tile is warp-private).  Lane<28: half-row
// (7 px).  Outputs staged into the (dead) tile then copied out coalesced;
// stats via warp reduce + 8 binned atomics.
__device__ __forceinline__ void warp_conv4(
    float* myfz, const float* __restrict__ wt2,
    uint2* __restrict__ dst, float* __restrict__ stats,
    int b, int lane, bool act)
{
    u64 acc[4][4];
    #pragma unroll
    for (int o = 0; o < 4; o++)
        #pragma unroll
        for (int p = 0; p < 4; p++) acc[o][p] = 0ull;

    if (act && lane < 28) {
        int row = lane >> 1, w0 = (lane & 1) * 7;
        const ulonglong2* wp2 = reinterpret_cast<const ulonglong2*>(wt2);
        #pragma unroll
        for (int ic = 0; ic < 4; ic++) {
            #pragma unroll
            for (int kh = 0; kh < 3; kh++) {
                const float* rp = myfz + (ic * 16 + row + kh) * FST + w0;
                float a[10];
                #pragma unroll
                for (int q = 0; q < 10; q++) a[q] = rp[q];
                u64 P[9];
                #pragma unroll
                for (int q = 0; q < 9; q++) P[q] = pack2(a[q], a[q + 1]);
                int wbase = (ic * 3 + kh) * 6;
                #pragma unroll
                for (int kw = 0; kw < 3; kw++) {
                    ulonglong2 wA = wp2[wbase + kw * 2];      // oc0, oc1
                    ulonglong2 wB = wp2[wbase + kw * 2 + 1];  // oc2, oc3
                    #pragma unroll
                    for (int p = 0; p < 4; p++) {
                        u64 pv = P[2 * p + kw];
                        acc[0][p] = fma2(pv, wA.x, acc[0][p]);
                        acc[1][p] = fma2(pv, wA.y, acc[1][p]);
                        acc[2][p] = fma2(pv, wB.x, acc[2][p]);
                        acc[3][p] = fma2(pv, wB.y, acc[3][p]);
                    }
                }
            }
        }
    }
    __syncwarp();                    // this warp's tile reads complete

    float s[8] = {0.f, 0.f, 0.f, 0.f, 0.f, 0.f, 0.f, 0.f};
    if (act && lane < 28) {
        #pragma unroll
        for (int o = 0; o < 4; o++) {
            float2 u0 = unpack2(acc[o][0]);
            float2 u1 = unpack2(acc[o][1]);
            float2 u2 = unpack2(acc[o][2]);
            float2 u3 = unpack2(acc[o][3]);   // .y garbage (px 7)
            float v[7] = {u0.x, u0.y, u1.x, u1.y, u2.x, u2.y, u3.x};
            float* op = myfz + o * 196 + lane * 7;
            #pragma unroll
            for (int j = 0; j < 7; j++) {
                op[j] = v[j];
                s[o]     += v[j];
                s[4 + o] += v[j] * v[j];
            }
        }
    }
    __syncwarp();
    if (act) {
        const float4* ob4 = reinterpret_cast<const float4*>(myfz);
        #pragma unroll
        for (int it = 0; it < 7; it++) {
            int j = it * 32 + lane;
            if (j < 196) {
                float4 v = ob4[j];
                HPack pk;
                pk.h[0] = __floats2half2_rn(v.x, v.y);
                pk.h[1] = __floats2half2_rn(v.z, v.w);
                dst[j] = pk.u;
            }
        }
    }
    #pragma unroll
    for (int off = 16; off; off >>= 1)
        #pragma unroll
        for (int c = 0; c < 8; c++)
            s[c] += __shfl_down_sync(0xffffffffu, s[c], off);
    if (act && lane == 0) {
        int base = (b & (NBIN - 1)) * 8;
        #pragma unroll
        for (int c = 0; c < 8; c++) atomicAdd(&stats[base + c], s[c]);
    }
}

__device__ __forceinline__ void bn_prologue(
    const float* __restrict__ stats, const float* __restrict__ gamma,
    const float* __restrict__ beta, float* sums8, float* sc, float* bi,
    int t, float Ninv)
{
    if (t < 8) {
        float s = 0.f;
        #pragma unroll
        for (int bin = 0; bin < NBIN; bin++) s += stats[bin * 8 + t];
        sums8[t] = s;
    }
    __syncthreads();
    if (t < 4) {
        float mean = sums8[t] * Ninv;
        float var  = sums8[4 + t] * Ninv - mean * mean;
        float s    = gamma[t] * rsqrtf(var + 1e-5f);
        sc[t] = s;
        bi[t] = beta[t] - mean * s;
    }
    __syncthreads();
}

// K1: quantum + conv1 + stats1.  1 warp/image, 4 images per 128-thr block.
// Block 0 also zeroes stats2 for this run (nothing reads stats2 during k1).
__global__ void __launch_bounds__(128) k_quanv_conv1(
    const float* __restrict__ x, const float* __restrict__ qw,
    const float* __restrict__ w1, int B)
{
    __shared__ __align__(16) float fz[4 * FIMG];
    __shared__ __align__(16) float wt2[288];
    int t = threadIdx.x, warp = t >> 5, lane = t & 31;
    int b = blockIdx.x * 4 + warp;
    bool act = (b < B);

    if (blockIdx.x == 0) {           // fold k_init: zero stats2
        stats2_g[t] = 0.f;
        stats2_g[t + 128] = 0.f;
    }

    // --- hoisted x loads (7 px-pairs per lane max) ---
    float2 xr0[7], xr1[7];
    const float* xb = x + (size_t)b * E;
    #pragma unroll
    for (int it = 0; it < 7; it++) {
        int p = it * 32 + lane;
        if (act && p < 196) {
            int i = p / 14, jj = p % 14;
            xr0[it] = *reinterpret_cast<const float2*>(xb + i * 56 + jj * 2);
            xr1[it] = *reinterpret_cast<const float2*>(xb + i * 56 + 28 + jj * 2);
        }
    }

    stage_weights(w1, wt2, t, 128);
    float* myfz = fz + warp * FIMG;
    float4* mz = reinterpret_cast<float4*>(myfz);
    for (int i = lane; i < FIMG / 4; i += 32)
        mz[i] = make_float4(0.f, 0.f, 0.f, 0.f);
    __syncwarp();

    if (act) {
        float q0 = qw[0], q1 = qw[1], q3 = qw[3], q4 = qw[4];
        float ct1 = __cosf(q1), ct3 = __cosf(q3);
        float st4, ct4; __sincosf(q4, &st4, &ct4);
        uint2* fdst = reinterpret_cast<uint2*>(f_h + (size_t)b * E);
        #pragma unroll
        for (int it = 0; it < 7; it++) {
            int p = it * 32 + lane;
            if (p < 196) {
                float sa, ca;   __sincosf(q0 + xr0[it].x, &sa, &ca);
                float sp1, cp1; __sincosf(xr0[it].y, &sp1, &cp1);
                float cp2 = __cosf(xr1[it].x), cp3 = __cosf(xr1[it].y);

                float m0 = ct4 * ca - st4 * sa * sp1;
                float m1 = ca * ct1 * cp1;
                float m2 = m1 * cp2;
                float m3 = ct3 * cp2 * cp3;

                HPack pk;
                pk.h[0] = __floats2half2_rn(m0, m1);
                pk.h[1] = __floats2half2_rn(m2, m3);
                fdst[p] = pk.u;

                float mv[4] = {m0, m1, m2, m3};
                #pragma unroll
                for (int q = 0; q < 4; q++) {
                    int e = p * 4 + q, c = e / 196, rr = e % 196;
                    myfz[(c * 16 + rr / 14 + 1) * FST + rr % 14 + 1] = mv[q];
                }
            }
        }
    }
    __syncwarp();
    // sync with weight staging done by other warps' threads
    __syncthreads();
    warp_conv4(myfz, wt2, reinterpret_cast<uint2*>(t1_h + (size_t)b * E),
               stats1_g, b, lane, act);
}

// K2: bn1+relu + conv2 + stats2.  1 warp/image, 4 images per 128-thr block.
__global__ void __launch_bounds__(128) k_conv2(
    const float* __restrict__ w2, const float* __restrict__ g1,
    const float* __restrict__ be1, int B)
{
    __shared__ __align__(16) float fz[4 * FIMG];
    __shared__ __align__(16) float wt2[288];
    __shared__ float sums8[8], sc[4], bi[4];
    int t = threadIdx.x, warp = t >> 5, lane = t & 31;
    int b = blockIdx.x * 4 + warp;
    bool act = (b < B);

    // --- hoisted t1 loads (7 uint2 per lane max) ---
    uint2 tv[7];
    const uint2* src = reinterpret_cast<const uint2*>(t1_h + (size_t)b * E);
    #pragma unroll
    for (int it = 0; it < 7; it++) {
        int j = it * 32 + lane;
        if (act && j < 196) tv[it] = src[j];
    }

    stage_weights(w2, wt2, t, 128);
    float* myfz = fz + warp * FIMG;
    float4* mz = reinterpret_cast<float4*>(myfz);
    for (int i = lane; i < FIMG / 4; i += 32)
        mz[i] = make_float4(0.f, 0.f, 0.f, 0.f);

    bn_prologue(stats1_g, g1, be1, sums8, sc, bi, t, 1.f / ((float)B * 196.f));

    if (act) {
        #pragma unroll
        for (int it = 0; it < 7; it++) {
            int e4 = it * 32 + lane;
            if (e4 < 196) {
                HPack pk; pk.u = tv[it];
                float2 lo = __half22float2(pk.h[0]);
                float2 hi = __half22float2(pk.h[1]);
                int c = e4 / 49;
                float s = sc[c], o = bi[c];
                float vv[4] = { fmaxf(lo.x*s+o, 0.f), fmaxf(lo.y*s+o, 0.f),
                                fmaxf(hi.x*s+o, 0.f), fmaxf(hi.y*s+o, 0.f) };
                int rr = (e4 * 4) % 196;
                #pragma unroll
                for (int q = 0; q < 4; q++) {
                    int rq = rr + q;
                    myfz[(c * 16 + rq / 14 + 1) * FST + rq % 14 + 1] = vv[q];
                }
            }
        }
    }
    __syncwarp();
    warp_conv4(myfz, wt2, reinterpret_cast<uint2*>(t2_h + (size_t)b * E),
               stats2_g, b, lane, act);
}

// K3: bn2 + residual + relu + fc + log_softmax.  2 images per warp (each fcw
// load feeds both), 8 images per 128-thr block.  Image A's t2/f hoisted;
// image B loaded inline.  Block 0 zeroes stats1 for the next run.
__global__ void __launch_bounds__(128) k_fc(
    const float* __restrict__ g2, const float* __restrict__ be2,
    const float* __restrict__ fcw, const float* __restrict__ fcb,
    float* __restrict__ out, int B)
{
    __shared__ float sums8[8], sc[4], bi[4];
    int t = threadIdx.x, warp = t >> 5, lane = t & 31;
    int b0 = blockIdx.x * 8 + warp * 2;
    bool a0 = (b0 < B), a1 = (b0 + 1 < B);
    int c0 = a0 ? b0 : 0, c1 = a1 ? b0 + 1 : c0;

    if (blockIdx.x == 0) {           // fold k_init: zero stats1 (dead here)
        stats1_g[t] = 0.f;
        stats1_g[t + 128] = 0.f;
    }

    // --- hoisted image-A loads ---
    uint2 tvA[7], fvA[7];
    const uint2* tA = reinterpret_cast<const uint2*>(t2_h + (size_t)c0 * E);
    const uint2* fA = reinterpret_cast<const uint2*>(f_h  + (size_t)c0 * E);
    #pragma unroll
    for (int it = 0; it < 7; it++) {
        int i = it * 32 + lane;
        if (a0 && i < 196) { tvA[it] = tA[i]; fvA[it] = fA[i]; }
    }

    bn_prologue(stats2_g, g2, be2, sums8, sc, bi, t, 1.f / ((float)B * 196.f));
    if (!a0) return;

    const uint2* tB = reinterpret_cast<const uint2*>(t2_h + (size_t)c1 * E);
    const uint2* fB = reinterpret_cast<const uint2*>(f_h  + (size_t)c1 * E);
    const float4* fw4 = reinterpret_cast<const float4*>(fcw);

    u64 accA[10], accB[10];
    #pragma unroll
    for (int k = 0; k < 10; k++) { accA[k] = 0ull; accB[k] = 0ull; }

    #pragma unroll
    for (int it = 0; it < 7; it++) {
        int i = it * 32 + lane;
        if (i < 196) {
            int c = i / 49;
            float s = sc[c], o = bi[c];

            HPack ta; ta.u = tvA[it];
            HPack fa; fa.u = fvA[it];
            float2 tl = __half22float2(ta.h[0]), th = __half22float2(ta.h[1]);
            float2 fl = __half22float2(fa.h[0]), fh = __half22float2(fa.h[1]);
            u64 A1 = pack2(fmaxf(tl.x*s+o+fl.x, 0.f), fmaxf(tl.y*s+o+fl.y, 0.f));
            u64 A2 = pack2(fmaxf(th.x*s+o+fh.x, 0.f), fmaxf(th.y*s+o+fh.y, 0.f));

            HPack tb; tb.u = tB[i];
            HPack fb; fb.u = fB[i];
            float2 ul = __half22float2(tb.h[0]), uh = __half22float2(tb.h[1]);
            float2 gl = __half22float2(fb.h[0]), gh = __half22float2(fb.h[1]);
            u64 B1 = pack2(fmaxf(ul.x*s+o+gl.x, 0.f), fmaxf(ul.y*s+o+gl.y, 0.f));
            u64 B2 = pack2(fmaxf(uh.x*s+o+gh.x, 0.f), fmaxf(uh.y*s+o+gh.y, 0.f));

            #pragma unroll
            for (int k = 0; k < 10; k++) {
                float4 wv = __ldg(&fw4[k * 196 + i]);
                u64 w1p = pack2(wv.x, wv.y), w2p = pack2(wv.z, wv.w);
                accA[k] = fma2(A1, w1p, accA[k]);
                accA[k] = fma2(A2, w2p, accA[k]);
                accB[k] = fma2(B1, w1p, accB[k]);
                accB[k] = fma2(B2, w2p, accB[k]);
            }
        }
    }
    float sA[10], sB[10];
    #pragma unroll
    for (int k = 0; k < 10; k++) {
        float2 ua = unpack2(accA[k]); sA[k] = ua.x + ua.y;
        float2 ub = unpack2(accB[k]); sB[k] = ub.x + ub.y;
    }
    #pragma unroll
    for (int off = 16; off; off >>= 1)
        #pragma unroll
        for (int k = 0; k < 10; k++) {
            sA[k] += __shfl_down_sync(0xffffffffu, sA[k], off);
            sB[k] += __shfl_down_sync(0xffffffffu, sB[k], off);
        }

    if (lane == 0) {
        float lg[10], mx = -1e30f;
        #pragma unroll
        for (int k = 0; k < 10; k++) {
            lg[k] = sA[k] + fcb[k];
            mx = fmaxf(mx, lg[k]);
        }
        float se = 0.f;
        #pragma unroll
        for (int k = 0; k < 10; k++) se += expf(lg[k] - mx);
        float lse = mx + logf(se);
        #pragma unroll
        for (int k = 0; k < 10; k++) out[(size_t)b0 * 10 + k] = lg[k] - lse;

        if (a1) {
            mx = -1e30f;
            #pragma unroll
            for (int k = 0; k < 10; k++) {
                lg[k] = sB[k] + fcb[k];
                mx = fmaxf(mx, lg[k]);
            }
            se = 0.f;
            #pragma unroll
            for (int k = 0; k < 10; k++) se += expf(lg[k] - mx);
            lse = mx + logf(se);
            #pragma unroll
            for (int k = 0; k < 10; k++)
                out[(size_t)(b0 + 1) * 10 + k] = lg[k] - lse;
        }
    }
}

extern "C" void kernel_launch(void* const* d_in, const int* in_sizes, int n_in,
                              void* d_out, int out_size)
{
    const float* x   = (const float*)d_in[0];
    const float* qw  = (const float*)d_in[1];
    const float* w1  = (const float*)d_in[2];
    const float* g1  = (const float*)d_in[3];
    const float* be1 = (const float*)d_in[4];
    const float* w2  = (const float*)d_in[5];
    const float* g2  = (const float*)d_in[6];
    const float* be2 = (const float*)d_in[7];
    const float* fcw = (const float*)d_in[8];
    const float* fcb = (const float*)d_in[9];
    float* out = (float*)d_out;

    int B = in_sizes[0] / E;
    if (B > MAXB) B = MAXB;

    k_quanv_conv1<<<(B + 3) / 4, 128>>>(x, qw, w1, B);
    k_conv2<<<(B + 3) / 4, 128>>>(w2, g1, be1, B);
    k_fc<<<(B + 7) / 8, 128>>>(g2, be2, fcw, fcb, out, B);
}